// round 3
// baseline (speedup 1.0000x reference)
#include <cuda_runtime.h>
#include <math.h>

#define BB 32
#define TT 64
#define HH 1024
#define VV 32000
#define G3H 3072
#define MROWS 2048  // TT*BB

// Scratch (static device allocations — allowed)
__device__ float g_GI[(size_t)MROWS * G3H];      // precomputed input gates, 25 MB
__device__ float g_Hist[(size_t)TT * BB * HH];   // hidden history, 8 MB
__device__ float g_lse[MROWS];                   // per-row logsumexp

// ---------------------------------------------------------------------------
// Kernel 1: GI[m][n] = relu(emb[tok(m)]) . W_ih[n] + b_ih[n]
// m = t*32 + b ; tok = (t==0) ? SOS(0) : target[b][t-1]
// Classic 128x128x8 sgemm, 256 threads, 8x8 per-thread microtile.
// NOTE: target_tensor is int32 on device (JAX x64 disabled).
// ---------------------------------------------------------------------------
__global__ __launch_bounds__(256) void gi_gemm_kernel(
    const int* __restrict__ target,
    const float* __restrict__ emb,
    const float* __restrict__ W_ih,
    const float* __restrict__ b_ih)
{
    __shared__ float As[8][132];
    __shared__ float Bs[8][132];
    int tid = threadIdx.x;
    int bm = blockIdx.y * 128;
    int bn = blockIdx.x * 128;

    int a_row = tid >> 1;
    int a_k4 = (tid & 1) << 2;

    int m = bm + a_row;
    int t = m >> 5;
    int b = m & 31;
    int tok = (t == 0) ? 0 : target[b * TT + t - 1];
    const float* Arow = emb + (size_t)tok * HH + a_k4;
    const float* Brow = W_ih + (size_t)(bn + a_row) * HH + a_k4;

    int tx = tid & 15, ty = tid >> 4;
    float acc[8][8];
    #pragma unroll
    for (int i = 0; i < 8; i++)
        #pragma unroll
        for (int j = 0; j < 8; j++) acc[i][j] = 0.f;

    for (int k0 = 0; k0 < HH; k0 += 8) {
        float4 av = *(const float4*)(Arow + k0);
        float4 bv = *(const float4*)(Brow + k0);
        av.x = fmaxf(av.x, 0.f); av.y = fmaxf(av.y, 0.f);
        av.z = fmaxf(av.z, 0.f); av.w = fmaxf(av.w, 0.f);
        __syncthreads();
        As[a_k4 + 0][a_row] = av.x;
        As[a_k4 + 1][a_row] = av.y;
        As[a_k4 + 2][a_row] = av.z;
        As[a_k4 + 3][a_row] = av.w;
        Bs[a_k4 + 0][a_row] = bv.x;
        Bs[a_k4 + 1][a_row] = bv.y;
        Bs[a_k4 + 2][a_row] = bv.z;
        Bs[a_k4 + 3][a_row] = bv.w;
        __syncthreads();
        #pragma unroll
        for (int kk = 0; kk < 8; kk++) {
            float a[8], bb[8];
            *(float4*)&a[0]  = *(const float4*)&As[kk][ty * 8];
            *(float4*)&a[4]  = *(const float4*)&As[kk][ty * 8 + 4];
            *(float4*)&bb[0] = *(const float4*)&Bs[kk][tx * 8];
            *(float4*)&bb[4] = *(const float4*)&Bs[kk][tx * 8 + 4];
            #pragma unroll
            for (int i = 0; i < 8; i++)
                #pragma unroll
                for (int j = 0; j < 8; j++)
                    acc[i][j] += a[i] * bb[j];
        }
    }

    #pragma unroll
    for (int i = 0; i < 8; i++) {
        int mm = bm + ty * 8 + i;
        float* dst = g_GI + (size_t)mm * G3H + bn + tx * 8;
        #pragma unroll
        for (int j = 0; j < 8; j += 4) {
            float4 v;
            v.x = acc[i][j + 0] + b_ih[bn + tx * 8 + j + 0];
            v.y = acc[i][j + 1] + b_ih[bn + tx * 8 + j + 1];
            v.z = acc[i][j + 2] + b_ih[bn + tx * 8 + j + 2];
            v.w = acc[i][j + 3] + b_ih[bn + tx * 8 + j + 3];
            *(float4*)(dst + j) = v;
        }
    }
}

// ---------------------------------------------------------------------------
// Kernel 2 (x64, sequential): one GRU step.
// grid = 128 blocks x 8 h-cols, block = 256 threads (lane = batch, warp = col).
// ---------------------------------------------------------------------------
__global__ __launch_bounds__(256) void gru_step_kernel(
    const float* __restrict__ enc_hidden,
    const float* __restrict__ W_hh,
    const float* __restrict__ b_hh,
    int t)
{
    __shared__ float hs[32][260];   // [batch][k-chunk], padded
    const float* h_in = (t == 0) ? enc_hidden : (g_Hist + (size_t)(t - 1) * BB * HH);
    float* h_out = g_Hist + (size_t)t * BB * HH;

    int tid = threadIdx.x;
    int lane = tid & 31;            // batch
    int w = tid >> 5;               // warp -> h column within block
    int j = blockIdx.x * 8 + w;     // 0..1023

    const float* Wr = W_hh + (size_t)j * HH;
    const float* Wz = W_hh + (size_t)(HH + j) * HH;
    const float* Wn = W_hh + (size_t)(2 * HH + j) * HH;

    float ar = 0.f, az = 0.f, an = 0.f;

    for (int k0 = 0; k0 < HH; k0 += 256) {
        for (int idx = tid; idx < 32 * 256; idx += 256) {
            int bb2 = idx >> 8;
            int kk = idx & 255;
            hs[bb2][kk] = h_in[bb2 * HH + k0 + kk];
        }
        __syncthreads();
        #pragma unroll 8
        for (int kk = 0; kk < 256; kk += 4) {
            float4 h4 = *(const float4*)&hs[lane][kk];
            float4 wr = *(const float4*)(Wr + k0 + kk);
            float4 wz = *(const float4*)(Wz + k0 + kk);
            float4 wn = *(const float4*)(Wn + k0 + kk);
            ar += h4.x * wr.x + h4.y * wr.y + h4.z * wr.z + h4.w * wr.w;
            az += h4.x * wz.x + h4.y * wz.y + h4.z * wz.z + h4.w * wz.w;
            an += h4.x * wn.x + h4.y * wn.y + h4.z * wn.z + h4.w * wn.w;
        }
        __syncthreads();
    }

    // GRU combine
    int mrow = t * BB + lane;
    const float* gi = g_GI + (size_t)mrow * G3H;
    float ir  = gi[j];
    float iz  = gi[HH + j];
    float inn = gi[2 * HH + j];
    float gr = ar + b_hh[j];
    float gz = az + b_hh[HH + j];
    float gn = an + b_hh[2 * HH + j];
    float r = 1.f / (1.f + expf(-(ir + gr)));
    float z = 1.f / (1.f + expf(-(iz + gz)));
    float n = tanhf(inn + r * gn);
    float ho = h_in[lane * HH + j];
    h_out[lane * HH + j] = (1.f - z) * n + z * ho;
}

// ---------------------------------------------------------------------------
// Kernel 3: logits = Hist @ fc_w^T + fc_b, written directly into d_out with
// the [b][t] row remap. Same 128x128x8 sgemm skeleton.
// ---------------------------------------------------------------------------
__global__ __launch_bounds__(256) void fc_gemm_kernel(
    const float* __restrict__ fc_w,
    const float* __restrict__ fc_b,
    float* __restrict__ out)
{
    __shared__ float As[8][132];
    __shared__ float Bs[8][132];
    int tid = threadIdx.x;
    int bm = blockIdx.y * 128;
    int bn = blockIdx.x * 128;

    int a_row = tid >> 1;
    int a_k4 = (tid & 1) << 2;

    const float* Arow = g_Hist + (size_t)(bm + a_row) * HH + a_k4;
    const float* Brow = fc_w + (size_t)(bn + a_row) * HH + a_k4;

    int tx = tid & 15, ty = tid >> 4;
    float acc[8][8];
    #pragma unroll
    for (int i = 0; i < 8; i++)
        #pragma unroll
        for (int j = 0; j < 8; j++) acc[i][j] = 0.f;

    for (int k0 = 0; k0 < HH; k0 += 8) {
        float4 av = *(const float4*)(Arow + k0);
        float4 bv = *(const float4*)(Brow + k0);
        __syncthreads();
        As[a_k4 + 0][a_row] = av.x;
        As[a_k4 + 1][a_row] = av.y;
        As[a_k4 + 2][a_row] = av.z;
        As[a_k4 + 3][a_row] = av.w;
        Bs[a_k4 + 0][a_row] = bv.x;
        Bs[a_k4 + 1][a_row] = bv.y;
        Bs[a_k4 + 2][a_row] = bv.z;
        Bs[a_k4 + 3][a_row] = bv.w;
        __syncthreads();
        #pragma unroll
        for (int kk = 0; kk < 8; kk++) {
            float a[8], bb[8];
            *(float4*)&a[0]  = *(const float4*)&As[kk][ty * 8];
            *(float4*)&a[4]  = *(const float4*)&As[kk][ty * 8 + 4];
            *(float4*)&bb[0] = *(const float4*)&Bs[kk][tx * 8];
            *(float4*)&bb[4] = *(const float4*)&Bs[kk][tx * 8 + 4];
            #pragma unroll
            for (int i = 0; i < 8; i++)
                #pragma unroll
                for (int j = 0; j < 8; j++)
                    acc[i][j] += a[i] * bb[j];
        }
    }

    #pragma unroll
    for (int i = 0; i < 8; i++) {
        int mm = bm + ty * 8 + i;       // m = t*32 + b
        int tstep = mm >> 5;
        int batch = mm & 31;
        size_t orow = (size_t)(batch * TT + tstep) * VV;
        float* dst = out + orow + bn + tx * 8;
        #pragma unroll
        for (int j = 0; j < 8; j += 4) {
            float4 v;
            v.x = acc[i][j + 0] + fc_b[bn + tx * 8 + j + 0];
            v.y = acc[i][j + 1] + fc_b[bn + tx * 8 + j + 1];
            v.z = acc[i][j + 2] + fc_b[bn + tx * 8 + j + 2];
            v.w = acc[i][j + 3] + fc_b[bn + tx * 8 + j + 3];
            *(float4*)(dst + j) = v;
        }
    }
}

// ---------------------------------------------------------------------------
// Kernel 4: per-row (2048 rows) online max + logsumexp over V=32000.
// ---------------------------------------------------------------------------
__global__ __launch_bounds__(256) void rowstats_kernel(const float* __restrict__ out)
{
    int r = blockIdx.x;
    const float* row = out + (size_t)r * VV;
    int tid = threadIdx.x;
    float m = -1e30f, s = 0.f;
    for (int i = tid; i < VV; i += 256) {
        float x = row[i];
        if (x > m) { s = s * expf(m - x) + 1.f; m = x; }
        else       { s += expf(x - m); }
    }
    __shared__ float sm[256], ss[256];
    sm[tid] = m; ss[tid] = s;
    __syncthreads();
    for (int off = 128; off > 0; off >>= 1) {
        if (tid < off) {
            float m1 = sm[tid], s1 = ss[tid];
            float m2 = sm[tid + off], s2 = ss[tid + off];
            float mm = fmaxf(m1, m2);
            sm[tid] = mm;
            ss[tid] = s1 * expf(m1 - mm) + s2 * expf(m2 - mm);
        }
        __syncthreads();
    }
    if (tid == 0) g_lse[r] = sm[0] + logf(ss[0]);
}

// ---------------------------------------------------------------------------
// Kernel 5: out = logits - lse[row]  (in-place, float4). Exactly covers B*T*V.
// ---------------------------------------------------------------------------
__global__ __launch_bounds__(256) void finalize_kernel(float* __restrict__ out)
{
    unsigned g = blockIdx.x * 256u + threadIdx.x;   // float4 index, < 16,384,000
    unsigned r = (g * 4u) / (unsigned)VV;
    float l = g_lse[r];
    float4 v = reinterpret_cast<float4*>(out)[g];
    v.x -= l; v.y -= l; v.z -= l; v.w -= l;
    reinterpret_cast<float4*>(out)[g] = v;
}

// ---------------------------------------------------------------------------
// Kernel 6: append final hidden state.
// ---------------------------------------------------------------------------
__global__ __launch_bounds__(256) void copy_hidden_kernel(float* __restrict__ out)
{
    int i = blockIdx.x * 256 + threadIdx.x;   // 0..32767
    out[(size_t)BB * TT * VV + i] = g_Hist[(size_t)(TT - 1) * BB * HH + i];
}

// ---------------------------------------------------------------------------
extern "C" void kernel_launch(void* const* d_in, const int* in_sizes, int n_in,
                              void* d_out, int out_size)
{
    (void)in_sizes; (void)n_in; (void)out_size;
    // metadata order:
    // 0 encoder_outputs (unused), 1 encoder_hidden, 2 target_tensor (int32!),
    // 3 emb, 4 W_ih, 5 W_hh, 6 b_ih, 7 b_hh, 8 fc_w, 9 fc_b
    const float* enc_hidden = (const float*)d_in[1];
    const int*   target     = (const int*)d_in[2];
    const float* emb        = (const float*)d_in[3];
    const float* W_ih       = (const float*)d_in[4];
    const float* W_hh       = (const float*)d_in[5];
    const float* b_ih       = (const float*)d_in[6];
    const float* b_hh       = (const float*)d_in[7];
    const float* fc_w       = (const float*)d_in[8];
    const float* fc_b       = (const float*)d_in[9];
    float* out = (float*)d_out;

    // Phase 1: all input gates (teacher forcing -> tokens known up front)
    gi_gemm_kernel<<<dim3(G3H / 128, MROWS / 128), 256>>>(target, emb, W_ih, b_ih);

    // Phase 2: sequential recurrence
    for (int t = 0; t < TT; t++)
        gru_step_kernel<<<128, 256>>>(enc_hidden, W_hh, b_hh, t);

    // Phase 3: FC projection into d_out (with [b][t] row remap)
    fc_gemm_kernel<<<dim3(VV / 128, MROWS / 128), 256>>>(fc_w, fc_b, out);

    // Phase 4: log_softmax in-place
    rowstats_kernel<<<MROWS, 256>>>(out);
    finalize_kernel<<<(BB * TT * VV / 4) / 256, 256>>>(out);

    // Phase 5: final hidden state
    copy_hidden_kernel<<<(BB * HH) / 256, 256>>>(out);
}

// round 8
// speedup vs baseline: 1.3418x; 1.3418x over previous
#include <cuda_runtime.h>
#include <math.h>

#define BB 32
#define TT 64
#define HH 1024
#define VV 32000
#define G3H 3072
#define MROWS 2048  // TT*BB

// Scratch (static device allocations — allowed)
__device__ float g_GI[(size_t)MROWS * G3H];      // precomputed input gates, 25 MB
__device__ float g_Hist[(size_t)TT * BB * HH];   // hidden history, 8 MB
__device__ float g_lse[MROWS];                   // per-row logsumexp
__device__ float g_GHp[2 * G3H * BB];            // K-split partial GH, 786 KB

// ---------------------------------------------------------------------------
// Kernel 1: GI[m][n] = relu(emb[tok(m)]) . W_ih[n] + b_ih[n]
// target_tensor is int32 on device (JAX x64 disabled).
// ---------------------------------------------------------------------------
__global__ __launch_bounds__(256) void gi_gemm_kernel(
    const int* __restrict__ target,
    const float* __restrict__ emb,
    const float* __restrict__ W_ih,
    const float* __restrict__ b_ih)
{
    __shared__ float As[8][132];
    __shared__ float Bs[8][132];
    int tid = threadIdx.x;
    int bm = blockIdx.y * 128;
    int bn = blockIdx.x * 128;

    int a_row = tid >> 1;
    int a_k4 = (tid & 1) << 2;

    int m = bm + a_row;
    int t = m >> 5;
    int b = m & 31;
    int tok = (t == 0) ? 0 : target[b * TT + t - 1];
    const float* Arow = emb + (size_t)tok * HH + a_k4;
    const float* Brow = W_ih + (size_t)(bn + a_row) * HH + a_k4;

    int tx = tid & 15, ty = tid >> 4;
    float acc[8][8];
    #pragma unroll
    for (int i = 0; i < 8; i++)
        #pragma unroll
        for (int j = 0; j < 8; j++) acc[i][j] = 0.f;

    for (int k0 = 0; k0 < HH; k0 += 8) {
        float4 av = *(const float4*)(Arow + k0);
        float4 bv = *(const float4*)(Brow + k0);
        av.x = fmaxf(av.x, 0.f); av.y = fmaxf(av.y, 0.f);
        av.z = fmaxf(av.z, 0.f); av.w = fmaxf(av.w, 0.f);
        __syncthreads();
        As[a_k4 + 0][a_row] = av.x;
        As[a_k4 + 1][a_row] = av.y;
        As[a_k4 + 2][a_row] = av.z;
        As[a_k4 + 3][a_row] = av.w;
        Bs[a_k4 + 0][a_row] = bv.x;
        Bs[a_k4 + 1][a_row] = bv.y;
        Bs[a_k4 + 2][a_row] = bv.z;
        Bs[a_k4 + 3][a_row] = bv.w;
        __syncthreads();
        #pragma unroll
        for (int kk = 0; kk < 8; kk++) {
            float a[8], bb[8];
            *(float4*)&a[0]  = *(const float4*)&As[kk][ty * 8];
            *(float4*)&a[4]  = *(const float4*)&As[kk][ty * 8 + 4];
            *(float4*)&bb[0] = *(const float4*)&Bs[kk][tx * 8];
            *(float4*)&bb[4] = *(const float4*)&Bs[kk][tx * 8 + 4];
            #pragma unroll
            for (int i = 0; i < 8; i++)
                #pragma unroll
                for (int j = 0; j < 8; j++)
                    acc[i][j] += a[i] * bb[j];
        }
    }

    #pragma unroll
    for (int i = 0; i < 8; i++) {
        int mm = bm + ty * 8 + i;
        float* dst = g_GI + (size_t)mm * G3H + bn + tx * 8;
        #pragma unroll
        for (int j = 0; j < 8; j += 4) {
            float4 v;
            v.x = acc[i][j + 0] + b_ih[bn + tx * 8 + j + 0];
            v.y = acc[i][j + 1] + b_ih[bn + tx * 8 + j + 1];
            v.z = acc[i][j + 2] + b_ih[bn + tx * 8 + j + 2];
            v.w = acc[i][j + 3] + b_ih[bn + tx * 8 + j + 3];
            *(float4*)(dst + j) = v;
        }
    }
}

// ---------------------------------------------------------------------------
// Kernel 2a (x64): GH partials = W_hh[rows] . h^T, tiled GEMM.
// grid = (64 rowblocks of 48 rows) x (2 K-splits of 512). block = 256 (8 warps).
// Warp handles 6 rows x 32 batches (lane = batch). W broadcast from smem,
// h read conflict-free from transposed smem. Software-pipelined chunks.
// ---------------------------------------------------------------------------
#define GRU_ROWS 48
#define GRU_KC 64
#define GRU_KSPLIT 512

__global__ __launch_bounds__(256) void gru_gemm_kernel(
    const float* __restrict__ enc_hidden,
    const float* __restrict__ W_hh,
    int t)
{
    __shared__ float Ws[GRU_ROWS][68];     // [row][k], padded (272B rows, 16B aligned)
    __shared__ float hs[GRU_KC][33];       // [k][batch], stride 33 -> conflict-free

    const float* h_in = (t == 0) ? enc_hidden : (g_Hist + (size_t)(t - 1) * BB * HH);

    int tid  = threadIdx.x;
    int warp = tid >> 5;
    int lane = tid & 31;                   // batch
    int row0 = blockIdx.x * GRU_ROWS;      // global W row base
    int k0   = blockIdx.y * GRU_KSPLIT;    // K-split base

    float4 wreg[3];
    float  hreg[8];
    int hk = tid & 63;
    int hb0 = tid >> 6;                    // 0..3

    // prefetch chunk 0
    {
        int koff = k0;
        #pragma unroll
        for (int j = 0; j < 3; j++) {
            int f4 = tid + 256 * j;
            int r  = f4 >> 4;
            int kp = (f4 & 15) << 2;
            wreg[j] = *(const float4*)(W_hh + (size_t)(row0 + r) * HH + koff + kp);
        }
        #pragma unroll
        for (int p = 0; p < 8; p++)
            hreg[p] = h_in[(hb0 + p * 4) * HH + koff + hk];
    }

    float acc[6];
    #pragma unroll
    for (int r = 0; r < 6; r++) acc[r] = 0.f;
    int rbase = warp * 6;

    for (int c = 0; c < GRU_KSPLIT / GRU_KC; c++) {
        __syncthreads();   // prior compute done reading smem
        #pragma unroll
        for (int j = 0; j < 3; j++) {
            int f4 = tid + 256 * j;
            int r  = f4 >> 4;
            int kp = (f4 & 15) << 2;
            *(float4*)&Ws[r][kp] = wreg[j];
        }
        #pragma unroll
        for (int p = 0; p < 8; p++)
            hs[hk][hb0 + p * 4] = hreg[p];
        __syncthreads();

        if (c < GRU_KSPLIT / GRU_KC - 1) {
            int koff = k0 + (c + 1) * GRU_KC;
            #pragma unroll
            for (int j = 0; j < 3; j++) {
                int f4 = tid + 256 * j;
                int r  = f4 >> 4;
                int kp = (f4 & 15) << 2;
                wreg[j] = *(const float4*)(W_hh + (size_t)(row0 + r) * HH + koff + kp);
            }
            #pragma unroll
            for (int p = 0; p < 8; p++)
                hreg[p] = h_in[(hb0 + p * 4) * HH + koff + hk];
        }

        #pragma unroll
        for (int k4 = 0; k4 < GRU_KC / 4; k4++) {
            float h0 = hs[k4 * 4 + 0][lane];
            float h1 = hs[k4 * 4 + 1][lane];
            float h2 = hs[k4 * 4 + 2][lane];
            float h3 = hs[k4 * 4 + 3][lane];
            #pragma unroll
            for (int r = 0; r < 6; r++) {
                float4 w = *(const float4*)&Ws[rbase + r][k4 * 4];
                acc[r] += w.x * h0;
                acc[r] += w.y * h1;
                acc[r] += w.z * h2;
                acc[r] += w.w * h3;
            }
        }
    }

    float* dst = g_GHp + (size_t)blockIdx.y * G3H * BB;
    #pragma unroll
    for (int r = 0; r < 6; r++) {
        int grow = row0 + rbase + r;
        dst[grow * BB + lane] = acc[r];
    }
}

// ---------------------------------------------------------------------------
// Kernel 2b (x64): combine GH partials + GI + biases -> h_new = Hist[t].
// 32K threads; thread -> (batch b = i>>10, col j = i&1023).
// ---------------------------------------------------------------------------
__global__ __launch_bounds__(256) void gru_combine_kernel(
    const float* __restrict__ enc_hidden,
    const float* __restrict__ b_hh,
    int t)
{
    int i = blockIdx.x * 256 + threadIdx.x;   // 0..32767
    int b = i >> 10;
    int j = i & 1023;

    const float* h_in = (t == 0) ? enc_hidden : (g_Hist + (size_t)(t - 1) * BB * HH);

    const float* P0 = g_GHp;
    const float* P1 = g_GHp + (size_t)G3H * BB;
    float gr = P0[j * BB + b]            + P1[j * BB + b]            + b_hh[j];
    float gz = P0[(HH + j) * BB + b]     + P1[(HH + j) * BB + b]     + b_hh[HH + j];
    float gn = P0[(2 * HH + j) * BB + b] + P1[(2 * HH + j) * BB + b] + b_hh[2 * HH + j];

    const float* gi = g_GI + (size_t)(t * BB + b) * G3H;
    float ir  = gi[j];
    float iz  = gi[HH + j];
    float inn = gi[2 * HH + j];

    float r = 1.f / (1.f + expf(-(ir + gr)));
    float z = 1.f / (1.f + expf(-(iz + gz)));
    float n = tanhf(inn + r * gn);
    float ho = h_in[b * HH + j];
    g_Hist[(size_t)t * BB * HH + b * HH + j] = (1.f - z) * n + z * ho;
}

// ---------------------------------------------------------------------------
// Kernel 3: logits = Hist @ fc_w^T + fc_b, into d_out with [b][t] remap.
// ---------------------------------------------------------------------------
__global__ __launch_bounds__(256) void fc_gemm_kernel(
    const float* __restrict__ fc_w,
    const float* __restrict__ fc_b,
    float* __restrict__ out)
{
    __shared__ float As[8][132];
    __shared__ float Bs[8][132];
    int tid = threadIdx.x;
    int bm = blockIdx.y * 128;
    int bn = blockIdx.x * 128;

    int a_row = tid >> 1;
    int a_k4 = (tid & 1) << 2;

    const float* Arow = g_Hist + (size_t)(bm + a_row) * HH + a_k4;
    const float* Brow = fc_w + (size_t)(bn + a_row) * HH + a_k4;

    int tx = tid & 15, ty = tid >> 4;
    float acc[8][8];
    #pragma unroll
    for (int i = 0; i < 8; i++)
        #pragma unroll
        for (int j = 0; j < 8; j++) acc[i][j] = 0.f;

    for (int k0 = 0; k0 < HH; k0 += 8) {
        float4 av = *(const float4*)(Arow + k0);
        float4 bv = *(const float4*)(Brow + k0);
        __syncthreads();
        As[a_k4 + 0][a_row] = av.x;
        As[a_k4 + 1][a_row] = av.y;
        As[a_k4 + 2][a_row] = av.z;
        As[a_k4 + 3][a_row] = av.w;
        Bs[a_k4 + 0][a_row] = bv.x;
        Bs[a_k4 + 1][a_row] = bv.y;
        Bs[a_k4 + 2][a_row] = bv.z;
        Bs[a_k4 + 3][a_row] = bv.w;
        __syncthreads();
        #pragma unroll
        for (int kk = 0; kk < 8; kk++) {
            float a[8], bb[8];
            *(float4*)&a[0]  = *(const float4*)&As[kk][ty * 8];
            *(float4*)&a[4]  = *(const float4*)&As[kk][ty * 8 + 4];
            *(float4*)&bb[0] = *(const float4*)&Bs[kk][tx * 8];
            *(float4*)&bb[4] = *(const float4*)&Bs[kk][tx * 8 + 4];
            #pragma unroll
            for (int i = 0; i < 8; i++)
                #pragma unroll
                for (int j = 0; j < 8; j++)
                    acc[i][j] += a[i] * bb[j];
        }
    }

    #pragma unroll
    for (int i = 0; i < 8; i++) {
        int mm = bm + ty * 8 + i;       // m = t*32 + b
        int tstep = mm >> 5;
        int batch = mm & 31;
        size_t orow = (size_t)(batch * TT + tstep) * VV;
        float* dst = out + orow + bn + tx * 8;
        #pragma unroll
        for (int j = 0; j < 8; j += 4) {
            float4 v;
            v.x = acc[i][j + 0] + fc_b[bn + tx * 8 + j + 0];
            v.y = acc[i][j + 1] + fc_b[bn + tx * 8 + j + 1];
            v.z = acc[i][j + 2] + fc_b[bn + tx * 8 + j + 2];
            v.w = acc[i][j + 3] + fc_b[bn + tx * 8 + j + 3];
            *(float4*)(dst + j) = v;
        }
    }
}

// ---------------------------------------------------------------------------
// Kernel 4: per-row online max + logsumexp over V=32000.
// ---------------------------------------------------------------------------
__global__ __launch_bounds__(256) void rowstats_kernel(const float* __restrict__ out)
{
    int r = blockIdx.x;
    const float* row = out + (size_t)r * VV;
    int tid = threadIdx.x;
    float m = -1e30f, s = 0.f;
    for (int i = tid; i < VV; i += 256) {
        float x = row[i];
        if (x > m) { s = s * expf(m - x) + 1.f; m = x; }
        else       { s += expf(x - m); }
    }
    __shared__ float sm[256], ss[256];
    sm[tid] = m; ss[tid] = s;
    __syncthreads();
    for (int off = 128; off > 0; off >>= 1) {
        if (tid < off) {
            float m1 = sm[tid], s1 = ss[tid];
            float m2 = sm[tid + off], s2 = ss[tid + off];
            float mm = fmaxf(m1, m2);
            sm[tid] = mm;
            ss[tid] = s1 * expf(m1 - mm) + s2 * expf(m2 - mm);
        }
        __syncthreads();
    }
    if (tid == 0) g_lse[r] = sm[0] + logf(ss[0]);
}

// ---------------------------------------------------------------------------
// Kernel 5: out -= lse[row]  (in-place, float4).
// ---------------------------------------------------------------------------
__global__ __launch_bounds__(256) void finalize_kernel(float* __restrict__ out)
{
    unsigned g = blockIdx.x * 256u + threadIdx.x;   // float4 index
    unsigned r = (g * 4u) / (unsigned)VV;
    float l = g_lse[r];
    float4 v = reinterpret_cast<float4*>(out)[g];
    v.x -= l; v.y -= l; v.z -= l; v.w -= l;
    reinterpret_cast<float4*>(out)[g] = v;
}

// ---------------------------------------------------------------------------
// Kernel 6: append final hidden state.
// ---------------------------------------------------------------------------
__global__ __launch_bounds__(256) void copy_hidden_kernel(float* __restrict__ out)
{
    int i = blockIdx.x * 256 + threadIdx.x;   // 0..32767
    out[(size_t)BB * TT * VV + i] = g_Hist[(size_t)(TT - 1) * BB * HH + i];
}

// ---------------------------------------------------------------------------
extern "C" void kernel_launch(void* const* d_in, const int* in_sizes, int n_in,
                              void* d_out, int out_size)
{
    (void)in_sizes; (void)n_in; (void)out_size;
    const float* enc_hidden = (const float*)d_in[1];
    const int*   target     = (const int*)d_in[2];
    const float* emb        = (const float*)d_in[3];
    const float* W_ih       = (const float*)d_in[4];
    const float* W_hh       = (const float*)d_in[5];
    const float* b_ih       = (const float*)d_in[6];
    const float* b_hh       = (const float*)d_in[7];
    const float* fc_w       = (const float*)d_in[8];
    const float* fc_b       = (const float*)d_in[9];
    float* out = (float*)d_out;

    // Phase 1: all input gates (teacher forcing -> tokens known up front)
    gi_gemm_kernel<<<dim3(G3H / 128, MROWS / 128), 256>>>(target, emb, W_ih, b_ih);

    // Phase 2: sequential recurrence (GEMM + combine per step)
    for (int t = 0; t < TT; t++) {
        gru_gemm_kernel<<<dim3(G3H / GRU_ROWS, 2), 256>>>(enc_hidden, W_hh, t);
        gru_combine_kernel<<<(BB * HH) / 256, 256>>>(enc_hidden, b_hh, t);
    }

    // Phase 3: FC projection into d_out (with [b][t] row remap)
    fc_gemm_kernel<<<dim3(VV / 128, MROWS / 128), 256>>>(fc_w, fc_b, out);

    // Phase 4: log_softmax in-place
    rowstats_kernel<<<MROWS, 256>>>(out);
    finalize_kernel<<<(BB * TT * VV / 4) / 256, 256>>>(out);

    // Phase 5: final hidden state
    copy_hidden_kernel<<<(BB * HH) / 256, 256>>>(out);
}

// round 10
// speedup vs baseline: 2.6834x; 1.9999x over previous
#include <cuda_runtime.h>
#include <cuda_bf16.h>
#include <math.h>
#include <stdint.h>

#define BB 32
#define TT 64
#define HH 1024
#define VV 32000
#define G3H 3072
#define MROWS 2048  // TT*BB

// ---------------------------------------------------------------------------
// Static device scratch
// ---------------------------------------------------------------------------
__device__ float g_GI[(size_t)MROWS * G3H];        // input gates, 25 MB
__device__ float g_Hist[(size_t)TT * BB * HH];     // hidden history, 8 MB
__device__ float g_lse[MROWS];                     // per-row logsumexp
__device__ float g_GHp[2 * G3H * BB];              // K-split partial GH

__device__ __nv_bfloat16 g_Abf[(size_t)MROWS * HH];  // bf16 hidden history
__device__ __nv_bfloat16 g_Wbf[(size_t)VV * HH];     // bf16 fc_w

// ---------------------------------------------------------------------------
// Helpers
// ---------------------------------------------------------------------------
__device__ __forceinline__ uint32_t smem_u32(const void* p) {
    uint32_t a;
    asm("{ .reg .u64 t; cvta.to.shared.u64 t, %1; cvt.u32.u64 %0, t; }" : "=r"(a) : "l"(p));
    return a;
}
#define CP_ASYNC16(dst, src) \
    asm volatile("cp.async.cg.shared.global [%0], [%1], 16;" :: "r"(dst), "l"(src))
#define CP_COMMIT() asm volatile("cp.async.commit_group;" ::: "memory")
#define CP_WAIT(n)  asm volatile("cp.async.wait_group %0;" :: "n"(n) : "memory")

__device__ __forceinline__ void ldmatrix_x4(uint32_t& r0, uint32_t& r1,
                                            uint32_t& r2, uint32_t& r3, uint32_t addr)
{
    asm volatile("ldmatrix.sync.aligned.m8n8.x4.shared.b16 {%0,%1,%2,%3}, [%4];"
                 : "=r"(r0), "=r"(r1), "=r"(r2), "=r"(r3) : "r"(addr));
}
__device__ __forceinline__ void mma_bf16(float* c, const uint32_t* a, const uint32_t* b)
{
    asm volatile(
        "mma.sync.aligned.m16n8k16.row.col.f32.bf16.bf16.f32 "
        "{%0,%1,%2,%3}, {%4,%5,%6,%7}, {%8,%9}, {%0,%1,%2,%3};"
        : "+f"(c[0]), "+f"(c[1]), "+f"(c[2]), "+f"(c[3])
        : "r"(a[0]), "r"(a[1]), "r"(a[2]), "r"(a[3]), "r"(b[0]), "r"(b[1]));
}

// ---------------------------------------------------------------------------
// hmma_gemm: C[M,N] = A[M,K]bf16 @ B[N,K]bf16^T + bias, fp32 accum.
// CTA = 128x128, K-chunk 64 (=128B rows), double-buffered cp.async.
// smem layout per row: 16B chunk s stored at slot s ^ (row & 7)  (conflict-free
// for both the cp.async stores and the ldmatrix 8-row phases).
// 8 warps = 2(M) x 4(N); warp tile 64x32. remap=1: out row = (m&31)*TT + (m>>5).
// ---------------------------------------------------------------------------
#define HM_SMEM (65536 + 1024)

__global__ __launch_bounds__(256) void hmma_gemm_kernel(
    const __nv_bfloat16* __restrict__ A, const __nv_bfloat16* __restrict__ B,
    const float* __restrict__ bias, float* __restrict__ outp,
    int remap, int Nstride)
{
    extern __shared__ char smem_raw[];
    uint32_t base = (smem_u32(smem_raw) + 1023u) & ~1023u;

    int tid  = threadIdx.x;
    int warp = tid >> 5;
    int lane = tid & 31;
    int m0 = blockIdx.x * 128;
    int n0 = blockIdx.y * 128;

    int wm = warp & 1;            // M half (64 rows)
    int wn = warp >> 1;           // N quarter (32 cols)

    // loader assignment: threads 0-127 -> A rows, 128-255 -> B rows
    int lrow = tid & 127;
    int lsel = tid >> 7;
    const __nv_bfloat16* grow_ptr =
        lsel ? (B + (size_t)(n0 + lrow) * HH) : (A + (size_t)(m0 + lrow) * HH);
    uint32_t sdst_row = (uint32_t)lsel * 16384u + (uint32_t)lrow * 128u;
    uint32_t slot_xor = (uint32_t)(lrow & 7) * 16u;

    // ldmatrix per-thread row constants
    int a_r[4], b_r[2];
    #pragma unroll
    for (int mi = 0; mi < 4; mi++) a_r[mi] = wm * 64 + mi * 16 + (lane & 15);
    #pragma unroll
    for (int nh = 0; nh < 2; nh++)
        b_r[nh] = wn * 32 + nh * 16 + ((lane >> 4) << 3) + (lane & 7);
    int a_csel = lane >> 4;          // 0/1 -> k8 halves
    int b_csel = (lane >> 3) & 1;

    float acc[4][4][4];
    #pragma unroll
    for (int mi = 0; mi < 4; mi++)
        #pragma unroll
        for (int ni = 0; ni < 4; ni++)
            #pragma unroll
            for (int q = 0; q < 4; q++) acc[mi][ni][q] = 0.f;

    // prologue: chunk 0 -> buf 0
    {
        const char* src = (const char*)grow_ptr;
        #pragma unroll
        for (int s = 0; s < 8; s++)
            CP_ASYNC16(base + sdst_row + (((uint32_t)s * 16u) ^ slot_xor), src + s * 16);
        CP_COMMIT();
    }

    for (int it = 0; it < 16; it++) {
        int buf = it & 1;
        if (it + 1 < 16) {
            const char* src = (const char*)(grow_ptr + (it + 1) * 64);
            uint32_t dst = base + (uint32_t)((it + 1) & 1) * 32768u + sdst_row;
            #pragma unroll
            for (int s = 0; s < 8; s++)
                CP_ASYNC16(dst + (((uint32_t)s * 16u) ^ slot_xor), src + s * 16);
            CP_COMMIT();
            CP_WAIT(1);      // chunk `it` resident
        } else {
            CP_WAIT(0);
        }
        __syncthreads();

        uint32_t abuf = base + (uint32_t)buf * 32768u;
        uint32_t bbuf = abuf + 16384u;

        #pragma unroll
        for (int k16 = 0; k16 < 4; k16++) {
            uint32_t af[4][4], bf[4][2];
            #pragma unroll
            for (int mi = 0; mi < 4; mi++) {
                int r = a_r[mi];
                uint32_t c16 = (uint32_t)(k16 * 2 + a_csel);
                uint32_t addr = abuf + (uint32_t)r * 128u + ((c16 ^ (uint32_t)(r & 7)) << 4);
                ldmatrix_x4(af[mi][0], af[mi][1], af[mi][2], af[mi][3], addr);
            }
            #pragma unroll
            for (int nh = 0; nh < 2; nh++) {
                int r = b_r[nh];
                uint32_t c16 = (uint32_t)(k16 * 2 + b_csel);
                uint32_t addr = bbuf + (uint32_t)r * 128u + ((c16 ^ (uint32_t)(r & 7)) << 4);
                ldmatrix_x4(bf[nh * 2][0], bf[nh * 2][1],
                            bf[nh * 2 + 1][0], bf[nh * 2 + 1][1], addr);
            }
            #pragma unroll
            for (int mi = 0; mi < 4; mi++)
                #pragma unroll
                for (int ni = 0; ni < 4; ni++)
                    mma_bf16(acc[mi][ni], af[mi], bf[ni]);
        }
        __syncthreads();
    }

    // epilogue: c frag (m16n8): {c0,c1} row g cols qc,qc+1 ; {c2,c3} row g+8
    int g  = lane >> 2;
    int qc = (lane & 3) * 2;
    #pragma unroll
    for (int mi = 0; mi < 4; mi++) {
        int grow = m0 + wm * 64 + mi * 16 + g;
        #pragma unroll
        for (int ni = 0; ni < 4; ni++) {
            int gcol = n0 + wn * 32 + ni * 8 + qc;
            float bx = bias[gcol], by = bias[gcol + 1];
            int r1 = grow, r2 = grow + 8;
            size_t o1, o2;
            if (remap) {
                o1 = (size_t)((r1 & 31) * TT + (r1 >> 5)) * (size_t)Nstride;
                o2 = (size_t)((r2 & 31) * TT + (r2 >> 5)) * (size_t)Nstride;
            } else {
                o1 = (size_t)r1 * (size_t)Nstride;
                o2 = (size_t)r2 * (size_t)Nstride;
            }
            float2 v1 = make_float2(acc[mi][ni][0] + bx, acc[mi][ni][1] + by);
            float2 v2 = make_float2(acc[mi][ni][2] + bx, acc[mi][ni][3] + by);
            *(float2*)(outp + o1 + gcol) = v1;
            *(float2*)(outp + o2 + gcol) = v2;
        }
    }
}

// ---------------------------------------------------------------------------
// fp32 -> bf16 convert (float4 per thread; grid covers count/4 exactly)
// ---------------------------------------------------------------------------
__global__ __launch_bounds__(256) void tobf16_kernel(
    const float* __restrict__ src, __nv_bfloat16* __restrict__ dst)
{
    size_t i = (size_t)blockIdx.x * 256 + threadIdx.x;
    float4 v = ((const float4*)src)[i];
    __nv_bfloat162* d2 = (__nv_bfloat162*)(dst + i * 4);
    d2[0] = __nv_bfloat162(__float2bfloat16(v.x), __float2bfloat16(v.y));
    d2[1] = __nv_bfloat162(__float2bfloat16(v.z), __float2bfloat16(v.w));
}

// ---------------------------------------------------------------------------
// Kernel 1: GI = relu(emb[tok]) @ W_ih^T + b_ih  (fp32 sgemm, exact — feeds
// the recurrence, keep full precision). 128x128x8 tiles.
// ---------------------------------------------------------------------------
__global__ __launch_bounds__(256) void gi_gemm_kernel(
    const int* __restrict__ target,
    const float* __restrict__ emb,
    const float* __restrict__ W_ih,
    const float* __restrict__ b_ih)
{
    __shared__ float As[8][132];
    __shared__ float Bs[8][132];
    int tid = threadIdx.x;
    int bm = blockIdx.y * 128;
    int bn = blockIdx.x * 128;

    int a_row = tid >> 1;
    int a_k4 = (tid & 1) << 2;

    int m = bm + a_row;
    int t = m >> 5;
    int b = m & 31;
    int tok = (t == 0) ? 0 : target[b * TT + t - 1];
    const float* Arow = emb + (size_t)tok * HH + a_k4;
    const float* Brow = W_ih + (size_t)(bn + a_row) * HH + a_k4;

    int tx = tid & 15, ty = tid >> 4;
    float acc[8][8];
    #pragma unroll
    for (int i = 0; i < 8; i++)
        #pragma unroll
        for (int j = 0; j < 8; j++) acc[i][j] = 0.f;

    for (int k0 = 0; k0 < HH; k0 += 8) {
        float4 av = *(const float4*)(Arow + k0);
        float4 bv = *(const float4*)(Brow + k0);
        av.x = fmaxf(av.x, 0.f); av.y = fmaxf(av.y, 0.f);
        av.z = fmaxf(av.z, 0.f); av.w = fmaxf(av.w, 0.f);
        __syncthreads();
        As[a_k4 + 0][a_row] = av.x;
        As[a_k4 + 1][a_row] = av.y;
        As[a_k4 + 2][a_row] = av.z;
        As[a_k4 + 3][a_row] = av.w;
        Bs[a_k4 + 0][a_row] = bv.x;
        Bs[a_k4 + 1][a_row] = bv.y;
        Bs[a_k4 + 2][a_row] = bv.z;
        Bs[a_k4 + 3][a_row] = bv.w;
        __syncthreads();
        #pragma unroll
        for (int kk = 0; kk < 8; kk++) {
            float a[8], bb[8];
            *(float4*)&a[0]  = *(const float4*)&As[kk][ty * 8];
            *(float4*)&a[4]  = *(const float4*)&As[kk][ty * 8 + 4];
            *(float4*)&bb[0] = *(const float4*)&Bs[kk][tx * 8];
            *(float4*)&bb[4] = *(const float4*)&Bs[kk][tx * 8 + 4];
            #pragma unroll
            for (int i = 0; i < 8; i++)
                #pragma unroll
                for (int j = 0; j < 8; j++)
                    acc[i][j] += a[i] * bb[j];
        }
    }

    #pragma unroll
    for (int i = 0; i < 8; i++) {
        int mm = bm + ty * 8 + i;
        float* dst = g_GI + (size_t)mm * G3H + bn + tx * 8;
        #pragma unroll
        for (int j = 0; j < 8; j += 4) {
            float4 v;
            v.x = acc[i][j + 0] + b_ih[bn + tx * 8 + j + 0];
            v.y = acc[i][j + 1] + b_ih[bn + tx * 8 + j + 1];
            v.z = acc[i][j + 2] + b_ih[bn + tx * 8 + j + 2];
            v.w = acc[i][j + 3] + b_ih[bn + tx * 8 + j + 3];
            *(float4*)(dst + j) = v;
        }
    }
}

// ---------------------------------------------------------------------------
// GRU recurrence (unchanged, fp32 exact)
// ---------------------------------------------------------------------------
#define GRU_ROWS 48
#define GRU_KC 64
#define GRU_KSPLIT 512

__global__ __launch_bounds__(256) void gru_gemm_kernel(
    const float* __restrict__ enc_hidden,
    const float* __restrict__ W_hh,
    int t)
{
    __shared__ float Ws[GRU_ROWS][68];
    __shared__ float hs[GRU_KC][33];

    const float* h_in = (t == 0) ? enc_hidden : (g_Hist + (size_t)(t - 1) * BB * HH);

    int tid  = threadIdx.x;
    int warp = tid >> 5;
    int lane = tid & 31;
    int row0 = blockIdx.x * GRU_ROWS;
    int k0   = blockIdx.y * GRU_KSPLIT;

    float4 wreg[3];
    float  hreg[8];
    int hk = tid & 63;
    int hb0 = tid >> 6;

    {
        int koff = k0;
        #pragma unroll
        for (int j = 0; j < 3; j++) {
            int f4 = tid + 256 * j;
            int r  = f4 >> 4;
            int kp = (f4 & 15) << 2;
            wreg[j] = *(const float4*)(W_hh + (size_t)(row0 + r) * HH + koff + kp);
        }
        #pragma unroll
        for (int p = 0; p < 8; p++)
            hreg[p] = h_in[(hb0 + p * 4) * HH + koff + hk];
    }

    float acc[6];
    #pragma unroll
    for (int r = 0; r < 6; r++) acc[r] = 0.f;
    int rbase = warp * 6;

    for (int c = 0; c < GRU_KSPLIT / GRU_KC; c++) {
        __syncthreads();
        #pragma unroll
        for (int j = 0; j < 3; j++) {
            int f4 = tid + 256 * j;
            int r  = f4 >> 4;
            int kp = (f4 & 15) << 2;
            *(float4*)&Ws[r][kp] = wreg[j];
        }
        #pragma unroll
        for (int p = 0; p < 8; p++)
            hs[hk][hb0 + p * 4] = hreg[p];
        __syncthreads();

        if (c < GRU_KSPLIT / GRU_KC - 1) {
            int koff = k0 + (c + 1) * GRU_KC;
            #pragma unroll
            for (int j = 0; j < 3; j++) {
                int f4 = tid + 256 * j;
                int r  = f4 >> 4;
                int kp = (f4 & 15) << 2;
                wreg[j] = *(const float4*)(W_hh + (size_t)(row0 + r) * HH + koff + kp);
            }
            #pragma unroll
            for (int p = 0; p < 8; p++)
                hreg[p] = h_in[(hb0 + p * 4) * HH + koff + hk];
        }

        #pragma unroll
        for (int k4 = 0; k4 < GRU_KC / 4; k4++) {
            float h0 = hs[k4 * 4 + 0][lane];
            float h1 = hs[k4 * 4 + 1][lane];
            float h2 = hs[k4 * 4 + 2][lane];
            float h3 = hs[k4 * 4 + 3][lane];
            #pragma unroll
            for (int r = 0; r < 6; r++) {
                float4 w = *(const float4*)&Ws[rbase + r][k4 * 4];
                acc[r] += w.x * h0;
                acc[r] += w.y * h1;
                acc[r] += w.z * h2;
                acc[r] += w.w * h3;
            }
        }
    }

    float* dst = g_GHp + (size_t)blockIdx.y * G3H * BB;
    #pragma unroll
    for (int r = 0; r < 6; r++) {
        int grow = row0 + rbase + r;
        dst[grow * BB + lane] = acc[r];
    }
}

__global__ __launch_bounds__(256) void gru_combine_kernel(
    const float* __restrict__ enc_hidden,
    const float* __restrict__ b_hh,
    int t)
{
    int i = blockIdx.x * 256 + threadIdx.x;
    int b = i >> 10;
    int j = i & 1023;

    const float* h_in = (t == 0) ? enc_hidden : (g_Hist + (size_t)(t - 1) * BB * HH);

    const float* P0 = g_GHp;
    const float* P1 = g_GHp + (size_t)G3H * BB;
    float gr = P0[j * BB + b]            + P1[j * BB + b]            + b_hh[j];
    float gz = P0[(HH + j) * BB + b]     + P1[(HH + j) * BB + b]     + b_hh[HH + j];
    float gn = P0[(2 * HH + j) * BB + b] + P1[(2 * HH + j) * BB + b] + b_hh[2 * HH + j];

    const float* gi = g_GI + (size_t)(t * BB + b) * G3H;
    float ir  = gi[j];
    float iz  = gi[HH + j];
    float inn = gi[2 * HH + j];

    float r = 1.f / (1.f + expf(-(ir + gr)));
    float z = 1.f / (1.f + expf(-(iz + gz)));
    float n = tanhf(inn + r * gn);
    float ho = h_in[b * HH + j];
    g_Hist[(size_t)t * BB * HH + b * HH + j] = (1.f - z) * n + z * ho;
}

// ---------------------------------------------------------------------------
// log_softmax + final hidden
// ---------------------------------------------------------------------------
__global__ __launch_bounds__(256) void rowstats_kernel(const float* __restrict__ out)
{
    int r = blockIdx.x;
    const float* row = out + (size_t)r * VV;
    int tid = threadIdx.x;
    float m = -1e30f, s = 0.f;
    for (int i = tid; i < VV; i += 256) {
        float x = row[i];
        if (x > m) { s = s * expf(m - x) + 1.f; m = x; }
        else       { s += expf(x - m); }
    }
    __shared__ float sm[256], ss[256];
    sm[tid] = m; ss[tid] = s;
    __syncthreads();
    for (int off = 128; off > 0; off >>= 1) {
        if (tid < off) {
            float m1 = sm[tid], s1 = ss[tid];
            float m2 = sm[tid + off], s2 = ss[tid + off];
            float mm = fmaxf(m1, m2);
            sm[tid] = mm;
            ss[tid] = s1 * expf(m1 - mm) + s2 * expf(m2 - mm);
        }
        __syncthreads();
    }
    if (tid == 0) g_lse[r] = sm[0] + logf(ss[0]);
}

__global__ __launch_bounds__(256) void finalize_kernel(float* __restrict__ out)
{
    unsigned g = blockIdx.x * 256u + threadIdx.x;
    unsigned r = (g * 4u) / (unsigned)VV;
    float l = g_lse[r];
    float4 v = reinterpret_cast<float4*>(out)[g];
    v.x -= l; v.y -= l; v.z -= l; v.w -= l;
    reinterpret_cast<float4*>(out)[g] = v;
}

__global__ __launch_bounds__(256) void copy_hidden_kernel(float* __restrict__ out)
{
    int i = blockIdx.x * 256 + threadIdx.x;
    out[(size_t)BB * TT * VV + i] = g_Hist[(size_t)(TT - 1) * BB * HH + i];
}

// ---------------------------------------------------------------------------
extern "C" void kernel_launch(void* const* d_in, const int* in_sizes, int n_in,
                              void* d_out, int out_size)
{
    (void)in_sizes; (void)n_in; (void)out_size;
    const float* enc_hidden = (const float*)d_in[1];
    const int*   target     = (const int*)d_in[2];
    const float* emb        = (const float*)d_in[3];
    const float* W_ih       = (const float*)d_in[4];
    const float* W_hh       = (const float*)d_in[5];
    const float* b_ih       = (const float*)d_in[6];
    const float* b_hh       = (const float*)d_in[7];
    const float* fc_w       = (const float*)d_in[8];
    const float* fc_b       = (const float*)d_in[9];
    float* out = (float*)d_out;

    cudaFuncSetAttribute(hmma_gemm_kernel,
                         cudaFuncAttributeMaxDynamicSharedMemorySize, HM_SMEM);

    void *pAbf, *pWbf, *pHist;
    cudaGetSymbolAddress(&pAbf, g_Abf);
    cudaGetSymbolAddress(&pWbf, g_Wbf);
    cudaGetSymbolAddress(&pHist, g_Hist);

    // Phase 0: fc_w -> bf16 (weight convert; overlaps nothing but is ~20us)
    tobf16_kernel<<<(VV * HH / 4) / 256, 256>>>(fc_w, (__nv_bfloat16*)pWbf);

    // Phase 1: GI = relu(emb[tok]) @ W_ih^T + b_ih  (fp32, exact)
    gi_gemm_kernel<<<dim3(G3H / 128, MROWS / 128), 256>>>(target, emb, W_ih, b_ih);

    // Phase 2: sequential recurrence (fp32, exact)
    for (int t = 0; t < TT; t++) {
        gru_gemm_kernel<<<dim3(G3H / GRU_ROWS, 2), 256>>>(enc_hidden, W_hh, t);
        gru_combine_kernel<<<(BB * HH) / 256, 256>>>(enc_hidden, b_hh, t);
    }

    // Phase 3: Hist -> bf16, then FC = Hist @ fc_w^T + fc_b on tensor cores
    tobf16_kernel<<<(MROWS * HH / 4) / 256, 256>>>((const float*)pHist,
                                                   (__nv_bfloat16*)pAbf);
    hmma_gemm_kernel<<<dim3(MROWS / 128, VV / 128), 256, HM_SMEM>>>(
        (const __nv_bfloat16*)pAbf, (const __nv_bfloat16*)pWbf,
        fc_b, out, 1, VV);

    // Phase 4: log_softmax in-place
    rowstats_kernel<<<MROWS, 256>>>(out);
    finalize_kernel<<<(BB * TT * VV / 4) / 256, 256>>>(out);

    // Phase 5: final hidden state
    copy_hidden_kernel<<<(BB * HH) / 256, 256>>>(out);
}